// round 5
// baseline (speedup 1.0000x reference)
#include <cuda_runtime.h>
#include <math.h>

// Problem constants
#define BB 16
#define MM 128
#define LL 32
#define SS 512
#define DD 768
#define HH 12
#define HD 64
#define DFF 3072
#define NL 4
#define NE 50000
#define NROWS (BB*MM)          // 2048
#define KPAD 128               // padded K for classifier stage 2

// ---------------- scratch (static device globals; no allocation) ----------------
__device__ __align__(16) float g_x[NROWS*DD];          // activations
__device__ __align__(16) float g_qkv[NROWS*3*DD];      // qkv proj
__device__ __align__(16) float g_attnout[NROWS*DD];    // merged-head attn output
__device__ __align__(16) float g_branch[NROWS*DD];     // residual branch
__device__ __align__(16) float g_ffh[NROWS*DFF];       // ffn hidden
__device__ __align__(16) float g_probs[BB*HH*MM*MM];   // raw attn scores scratch
__device__ __align__(16) float g_tpad[NROWS*KPAD];     // cls stage-1 out, K-padded
__device__ __align__(16) float g_w2pad[NE*KPAD];       // cls_w2 K-padded
__device__ __align__(16) float g_dl[BB*LL];            // per-(b,l) pooling dot

// ---------------- block reduction helper ----------------
__device__ __forceinline__ float block_reduce_sum(float v) {
    __shared__ float red[8];
    int lane = threadIdx.x & 31, wid = threadIdx.x >> 5, nw = (int)(blockDim.x >> 5);
    #pragma unroll
    for (int o = 16; o > 0; o >>= 1) v += __shfl_down_sync(0xffffffffu, v, o);
    __syncthreads();                 // protect red from a previous call's readers
    if (lane == 0) red[wid] = v;
    __syncthreads();
    float s = 0.f;
    for (int i = 0; i < nw; i++) s += red[i];
    return s;
}

// ---------------- mention pooling ----------------
// dl[b*L+l] = dot(lhs[b, l, :], attn_w)
__global__ void dot_kernel(const float* __restrict__ lhs, const float* __restrict__ aw,
                           float* __restrict__ dl) {
    int bl = blockIdx.x;                 // b*32 + l
    int b = bl >> 5, l = bl & 31;
    const float* r = lhs + ((size_t)b*SS + l)*DD;
    float s = 0.f;
    for (int d = threadIdx.x; d < DD; d += blockDim.x) s += r[d]*aw[d];
    s = block_reduce_sum(s);
    if (threadIdx.x == 0) dl[bl] = s;
}

// x[b,m,:] = sum_{l<vlen} softmax32(logits)_l * lhs[b,l,:]
// logits_l = (l<vlen ? dl[b,l] : 0) + attn_b ; softmax over all 32 slots
// NOTE: pos/mask are int32 (jax default config silently downcasts the
// reference's .astype(jnp.int64) to int32).
__global__ void pool_kernel(const float* __restrict__ lhs,
                            const int* __restrict__ pos,
                            const int* __restrict__ mask,
                            const float* __restrict__ dl,
                            const float* __restrict__ attn_b,
                            float* __restrict__ x) {
    int bm = blockIdx.x;                 // b*128 + m
    int b = bm >> 7;
    __shared__ float p[LL];
    __shared__ int s_vlen;
    if (threadIdx.x == 0) {
        int vlen = 0;
        if (mask[bm] != 0) {
            const int* pr = pos + (size_t)bm*LL;
            while (vlen < LL && pr[vlen] != -1) vlen++;
        }
        s_vlen = vlen;
        float ab = attn_b[0];
        float lg[LL];
        float mx = -INFINITY;
        for (int l = 0; l < LL; l++) {
            lg[l] = (l < vlen ? dl[b*LL + l] : 0.f) + ab;
            mx = fmaxf(mx, lg[l]);
        }
        float sum = 0.f;
        for (int l = 0; l < LL; l++) { float e = expf(lg[l]-mx); p[l] = e; sum += e; }
        float inv = 1.f/sum;
        for (int l = 0; l < LL; l++) p[l] *= inv;
    }
    __syncthreads();
    int vlen = s_vlen;
    float* xr = x + (size_t)bm*DD;
    for (int d = threadIdx.x; d < DD; d += blockDim.x) {
        float acc = 0.f;
        for (int l = 0; l < vlen; l++)
            acc += p[l] * lhs[((size_t)b*SS + l)*DD + d];
        xr[d] = acc;
    }
}

// ---------------- generic SGEMM: C[M,N] = A[M,K] * B[N,K]^T (+bias)(+relu) ----------------
// 128x128 tile, BK=8, 256 threads, 8x8 per-thread microtile.
// M must be a multiple of 128, K a multiple of 8, lda/ldb multiples of 4.
// Stores zeros for N <= n < Npad (used to zero-pad classifier K dim).
__global__ __launch_bounds__(256, 2)
void sgemm_nt(const float* __restrict__ A, const float* __restrict__ B,
              const float* __restrict__ bias, float* __restrict__ C,
              int M, int N, int K, int lda, int ldb, int ldc, int Npad, int relu) {
    __shared__ float As[8][128];
    __shared__ float Bs[8][128];
    int t = threadIdx.x;
    int m0 = blockIdx.y * 128;
    int n0 = blockIdx.x * 128;
    int lr = t >> 1;               // 0..127 tile row
    int lk = (t & 1) * 4;          // 0 or 4
    int tx = t & 15, ty = t >> 4;

    float acc[8][8];
    #pragma unroll
    for (int i = 0; i < 8; i++)
        #pragma unroll
        for (int j = 0; j < 8; j++) acc[i][j] = 0.f;

    const float* Aptr = A + (size_t)(m0 + lr)*lda + lk;
    bool bvalid = (n0 + lr) < N;
    const float* Bptr = B + (size_t)(n0 + lr)*ldb + lk;

    for (int k0 = 0; k0 < K; k0 += 8) {
        float4 a4 = *(const float4*)(Aptr + k0);
        float4 b4 = bvalid ? *(const float4*)(Bptr + k0) : make_float4(0.f,0.f,0.f,0.f);
        As[lk+0][lr] = a4.x; As[lk+1][lr] = a4.y; As[lk+2][lr] = a4.z; As[lk+3][lr] = a4.w;
        Bs[lk+0][lr] = b4.x; Bs[lk+1][lr] = b4.y; Bs[lk+2][lr] = b4.z; Bs[lk+3][lr] = b4.w;
        __syncthreads();
        #pragma unroll
        for (int kk = 0; kk < 8; kk++) {
            float af[8], bf[8];
            #pragma unroll
            for (int i = 0; i < 8; i++) af[i] = As[kk][ty*8 + i];
            #pragma unroll
            for (int j = 0; j < 8; j++) bf[j] = Bs[kk][tx*8 + j];
            #pragma unroll
            for (int i = 0; i < 8; i++)
                #pragma unroll
                for (int j = 0; j < 8; j++)
                    acc[i][j] += af[i]*bf[j];
        }
        __syncthreads();
    }

    #pragma unroll
    for (int i = 0; i < 8; i++) {
        int gm = m0 + ty*8 + i;
        #pragma unroll
        for (int j = 0; j < 8; j++) {
            int gn = n0 + tx*8 + j;
            if (gn < Npad) {
                float v = 0.f;
                if (gn < N) {
                    v = acc[i][j] + (bias ? bias[gn] : 0.f);
                    if (relu) v = fmaxf(v, 0.f);
                }
                C[(size_t)gm*ldc + gn] = v;
            }
        }
    }
}

// ---------------- attention (one block per (b,h), 128 threads = 128 queries) ----------------
__global__ __launch_bounds__(128)
void attn_kernel(const float* __restrict__ qkv, float* __restrict__ probs,
                 float* __restrict__ attnout) {
    __shared__ float Ks[128][64];
    int bh = blockIdx.x;
    int b = bh / HH, h = bh % HH;
    int t = threadIdx.x;
    const float* base = qkv + (size_t)b*MM*(3*DD);
    // stage K
    for (int idx = t; idx < 128*64; idx += 128) {
        int j = idx >> 6, d = idx & 63;
        Ks[j][d] = base[(size_t)j*(3*DD) + DD + h*HD + d];
    }
    __syncthreads();
    // q row into registers
    float q[64];
    const float* qrow = base + (size_t)t*(3*DD) + h*HD;
    #pragma unroll
    for (int d0 = 0; d0 < 64; d0 += 4) {
        float4 v = *(const float4*)(qrow + d0);
        q[d0] = v.x; q[d0+1] = v.y; q[d0+2] = v.z; q[d0+3] = v.w;
    }
    float mx = -INFINITY;
    float* prow = probs + (size_t)bh*MM*MM;
    const float scale = 0.125f;   // 1/sqrt(64)
    for (int j = 0; j < 128; j++) {
        float s = 0.f;
        #pragma unroll
        for (int d = 0; d < 64; d++) s += q[d]*Ks[j][d];
        s *= scale;
        mx = fmaxf(mx, s);
        prow[(size_t)j*128 + t] = s;   // transposed -> coalesced
    }
    __syncthreads();
    // stage V over K
    for (int idx = t; idx < 128*64; idx += 128) {
        int j = idx >> 6, d = idx & 63;
        Ks[j][d] = base[(size_t)j*(3*DD) + 2*DD + h*HD + d];
    }
    __syncthreads();
    float acc[64];
    #pragma unroll
    for (int d = 0; d < 64; d++) acc[d] = 0.f;
    float sum = 0.f;
    for (int j = 0; j < 128; j++) {
        float p = expf(prow[(size_t)j*128 + t] - mx);
        sum += p;
        #pragma unroll
        for (int d = 0; d < 64; d++) acc[d] += p*Ks[j][d];
    }
    float inv = 1.f/sum;
    float* orow = attnout + (size_t)(b*MM + t)*DD + h*HD;
    #pragma unroll
    for (int d = 0; d < 64; d++) orow[d] = acc[d]*inv;
}

// ---------------- fused residual + layernorm (in-place into x) ----------------
__global__ void add_ln_kernel(float* __restrict__ x, const float* __restrict__ y,
                              const float* __restrict__ w, const float* __restrict__ b) {
    __shared__ float buf[DD];
    int row = blockIdx.x, t = threadIdx.x;
    float* xr = x + (size_t)row*DD;
    const float* yr = y + (size_t)row*DD;
    float ls = 0.f;
    for (int d = t; d < DD; d += blockDim.x) {
        float v = xr[d] + yr[d];
        buf[d] = v;
        ls += v;
    }
    float mean = block_reduce_sum(ls) * (1.f/DD);
    float lv = 0.f;
    for (int d = t; d < DD; d += blockDim.x) {
        float c = buf[d] - mean;
        lv += c*c;
    }
    float var = block_reduce_sum(lv) * (1.f/DD);
    float r = rsqrtf(var + 1e-5f);
    for (int d = t; d < DD; d += blockDim.x)
        xr[d] = (buf[d] - mean)*r*w[d] + b[d];
}

// ---------------- pad cls_w2 [NE,100] -> [NE,128] ----------------
__global__ void pad_w2_kernel(const float* __restrict__ w2, float* __restrict__ w2p) {
    size_t i = (size_t)blockIdx.x*blockDim.x + threadIdx.x;
    if (i < (size_t)NE*KPAD) {
        int r = (int)(i >> 7), c = (int)(i & 127);
        w2p[i] = (c < 100) ? w2[(size_t)r*100 + c] : 0.f;
    }
}

// ---------------- launch ----------------
extern "C" void kernel_launch(void* const* d_in, const int* in_sizes, int n_in,
                              void* d_out, int out_size) {
    (void)in_sizes; (void)n_in; (void)out_size;
    const float* lhs    = (const float*)d_in[0];
    const int*   pos    = (const int*)d_in[1];     // int32 (jax x64 disabled)
    const int*   mask   = (const int*)d_in[2];     // int32
    const float* attn_w = (const float*)d_in[3];
    const float* attn_b = (const float*)d_in[4];
    const float* qkv_w  = (const float*)d_in[5];
    const float* qkv_b  = (const float*)d_in[6];
    const float* out_w  = (const float*)d_in[7];
    const float* out_b  = (const float*)d_in[8];
    const float* ln1_w  = (const float*)d_in[9];
    const float* ln1_b  = (const float*)d_in[10];
    const float* ff1_w  = (const float*)d_in[11];
    const float* ff1_b  = (const float*)d_in[12];
    const float* ff2_w  = (const float*)d_in[13];
    const float* ff2_b  = (const float*)d_in[14];
    const float* ln2_w  = (const float*)d_in[15];
    const float* ln2_b  = (const float*)d_in[16];
    const float* cls_w1 = (const float*)d_in[17];
    const float* cls_w2 = (const float*)d_in[18];
    const float* cls_b2 = (const float*)d_in[19];
    float* out = (float*)d_out;

    float *x, *qkv, *attnout, *branch, *ffh, *probs, *tpad, *w2pad, *dl;
    cudaGetSymbolAddress((void**)&x,       g_x);
    cudaGetSymbolAddress((void**)&qkv,     g_qkv);
    cudaGetSymbolAddress((void**)&attnout, g_attnout);
    cudaGetSymbolAddress((void**)&branch,  g_branch);
    cudaGetSymbolAddress((void**)&ffh,     g_ffh);
    cudaGetSymbolAddress((void**)&probs,   g_probs);
    cudaGetSymbolAddress((void**)&tpad,    g_tpad);
    cudaGetSymbolAddress((void**)&w2pad,   g_w2pad);
    cudaGetSymbolAddress((void**)&dl,      g_dl);

    // classifier weight padding (deterministic; part of every launch)
    pad_w2_kernel<<<(NE*KPAD + 255)/256, 256>>>(cls_w2, w2pad);

    // mention pooling
    dot_kernel<<<BB*LL, 128>>>(lhs, attn_w, dl);
    pool_kernel<<<NROWS, 256>>>(lhs, pos, mask, dl, attn_b, x);

    // transformer layers
    for (int i = 0; i < NL; i++) {
        sgemm_nt<<<dim3(18,16), 256>>>(x, qkv_w + (size_t)i*3*DD*DD, qkv_b + (size_t)i*3*DD,
                                       qkv, NROWS, 3*DD, DD, DD, DD, 3*DD, 3*DD, 0);
        attn_kernel<<<BB*HH, 128>>>(qkv, probs, attnout);
        sgemm_nt<<<dim3(6,16), 256>>>(attnout, out_w + (size_t)i*DD*DD, out_b + (size_t)i*DD,
                                      branch, NROWS, DD, DD, DD, DD, DD, DD, 0);
        add_ln_kernel<<<NROWS, 256>>>(x, branch, ln1_w + (size_t)i*DD, ln1_b + (size_t)i*DD);
        sgemm_nt<<<dim3(24,16), 256>>>(x, ff1_w + (size_t)i*DFF*DD, ff1_b + (size_t)i*DFF,
                                       ffh, NROWS, DFF, DD, DD, DD, DFF, DFF, 1);
        sgemm_nt<<<dim3(6,16), 256>>>(ffh, ff2_w + (size_t)i*DD*DFF, ff2_b + (size_t)i*DD,
                                      branch, NROWS, DD, DFF, DFF, DFF, DD, DD, 0);
        add_ln_kernel<<<NROWS, 256>>>(x, branch, ln2_w + (size_t)i*DD, ln2_b + (size_t)i*DD);
    }

    // classifier
    sgemm_nt<<<dim3(1,16), 256>>>(x, cls_w1, (const float*)nullptr, tpad,
                                  NROWS, 100, DD, DD, DD, KPAD, KPAD, 0);
    sgemm_nt<<<dim3((NE + 127)/128, 16), 256>>>(tpad, w2pad, cls_b2, out,
                                                NROWS, NE, KPAD, KPAD, KPAD, NE, NE, 0);
}

// round 6
// speedup vs baseline: 1.9681x; 1.9681x over previous
#include <cuda_runtime.h>
#include <math.h>
#include <stdint.h>

// Problem constants
#define BB 16
#define MM 128
#define LL 32
#define SS 512
#define DD 768
#define HH 12
#define HD 64
#define DFF 3072
#define NL 4
#define NE 50000
#define NROWS (BB*MM)          // 2048
#define KPAD 128               // padded K for classifier stage 2

// ---------------- scratch (static device globals; no allocation) ----------------
__device__ __align__(16) float g_x[NROWS*DD];          // activations
__device__ __align__(16) float g_qkv[NROWS*3*DD];      // qkv proj
__device__ __align__(16) float g_attnout[NROWS*DD];    // merged-head attn output
__device__ __align__(16) float g_branch[NROWS*DD];     // residual branch
__device__ __align__(16) float g_ffh[NROWS*DFF];       // ffn hidden
__device__ __align__(16) float g_probs[BB*HH*MM*MM];   // raw attn scores scratch
__device__ __align__(16) float g_tpad[NROWS*KPAD];     // cls stage-1 out, K-padded
__device__ __align__(16) float g_w2pad[NE*KPAD];       // cls_w2 K-padded
__device__ __align__(16) float g_dl[BB*LL];            // per-(b,l) pooling dot

// ---------------- block reduction helper ----------------
__device__ __forceinline__ float block_reduce_sum(float v) {
    __shared__ float red[8];
    int lane = threadIdx.x & 31, wid = threadIdx.x >> 5, nw = (int)(blockDim.x >> 5);
    #pragma unroll
    for (int o = 16; o > 0; o >>= 1) v += __shfl_down_sync(0xffffffffu, v, o);
    __syncthreads();
    if (lane == 0) red[wid] = v;
    __syncthreads();
    float s = 0.f;
    for (int i = 0; i < nw; i++) s += red[i];
    return s;
}

// ---------------- mention pooling ----------------
__global__ void dot_kernel(const float* __restrict__ lhs, const float* __restrict__ aw,
                           float* __restrict__ dl) {
    int bl = blockIdx.x;                 // b*32 + l
    int b = bl >> 5, l = bl & 31;
    const float* r = lhs + ((size_t)b*SS + l)*DD;
    float s = 0.f;
    for (int d = threadIdx.x; d < DD; d += blockDim.x) s += r[d]*aw[d];
    s = block_reduce_sum(s);
    if (threadIdx.x == 0) dl[bl] = s;
}

// pos/mask are int32 (jax x64 disabled silently downcasts the int64 cast).
__global__ void pool_kernel(const float* __restrict__ lhs,
                            const int* __restrict__ pos,
                            const int* __restrict__ mask,
                            const float* __restrict__ dl,
                            const float* __restrict__ attn_b,
                            float* __restrict__ x) {
    int bm = blockIdx.x;                 // b*128 + m
    int b = bm >> 7;
    __shared__ float p[LL];
    __shared__ int s_vlen;
    if (threadIdx.x == 0) {
        int vlen = 0;
        if (mask[bm] != 0) {
            const int* pr = pos + (size_t)bm*LL;
            while (vlen < LL && pr[vlen] != -1) vlen++;
        }
        s_vlen = vlen;
        float ab = attn_b[0];
        float lg[LL];
        float mx = -INFINITY;
        for (int l = 0; l < LL; l++) {
            lg[l] = (l < vlen ? dl[b*LL + l] : 0.f) + ab;
            mx = fmaxf(mx, lg[l]);
        }
        float sum = 0.f;
        for (int l = 0; l < LL; l++) { float e = expf(lg[l]-mx); p[l] = e; sum += e; }
        float inv = 1.f/sum;
        for (int l = 0; l < LL; l++) p[l] *= inv;
    }
    __syncthreads();
    int vlen = s_vlen;
    float* xr = x + (size_t)bm*DD;
    for (int d = threadIdx.x; d < DD; d += blockDim.x) {
        float acc = 0.f;
        for (int l = 0; l < vlen; l++)
            acc += p[l] * lhs[((size_t)b*SS + l)*DD + d];
        xr[d] = acc;
    }
}

// ---------------- tf32 tensor-core GEMM ----------------
// C[M,N] = A[M,K] * B[N,K]^T (+bias)(+relu), fp32 accumulate via
// mma.sync.aligned.m16n8k8.row.col.f32.tf32.tf32.f32.
// 128x128 block tile, BK=16, 256 threads = 8 warps (2m x 4n), warp tile 64x32.
// M multiple of 128, K multiple of 16, lda/ldb multiples of 4.
// Stores zeros for N <= n < Npad.

__device__ __forceinline__ uint32_t f2tf32(float x) {
    uint32_t y;
    asm("cvt.rna.tf32.f32 %0, %1;" : "=r"(y) : "f"(x));
    return y;
}

__device__ __forceinline__ void mma_tf32(float* c, const uint32_t* a, const uint32_t* b) {
    asm volatile(
        "mma.sync.aligned.m16n8k8.row.col.f32.tf32.tf32.f32 "
        "{%0,%1,%2,%3}, {%4,%5,%6,%7}, {%8,%9}, {%0,%1,%2,%3};\n"
        : "+f"(c[0]), "+f"(c[1]), "+f"(c[2]), "+f"(c[3])
        : "r"(a[0]), "r"(a[1]), "r"(a[2]), "r"(a[3]), "r"(b[0]), "r"(b[1]));
}

#define SMS 136   // smem row stride in words; 136 % 32 == 8 -> conflict-free

__global__ __launch_bounds__(256)
void tgemm_nt(const float* __restrict__ A, const float* __restrict__ B,
              const float* __restrict__ bias, float* __restrict__ C,
              int M, int N, int K, int lda, int ldb, int ldc, int Npad, int relu) {
    __shared__ uint32_t As[16][SMS];   // [k][m]
    __shared__ uint32_t Bs[16][SMS];   // [k][n]
    int t = threadIdx.x;
    int m0 = blockIdx.y * 128;
    int n0 = blockIdx.x * 128;

    // staging: each thread owns one 32B chunk: row lr, k cols lk..lk+7
    int lr = t & 127;
    int lk = (t >> 7) * 8;
    const float* Aptr = A + (size_t)(m0 + lr)*lda + lk;
    bool bv = (n0 + lr) < N;
    const float* Bptr = B + (size_t)(n0 + lr)*ldb + lk;

    int warp  = t >> 5, lane = t & 31;
    int group = lane >> 2, tg = lane & 3;
    int wm = (warp >> 2) * 64;   // 0 / 64
    int wn = (warp & 3) * 32;    // 0..96

    float acc[4][4][4];
    #pragma unroll
    for (int mi = 0; mi < 4; mi++)
        #pragma unroll
        for (int ni = 0; ni < 4; ni++)
            #pragma unroll
            for (int r = 0; r < 4; r++) acc[mi][ni][r] = 0.f;

    // preload first tile
    float4 pa0 = *(const float4*)(Aptr + 0);
    float4 pa1 = *(const float4*)(Aptr + 4);
    float4 pb0 = bv ? *(const float4*)(Bptr + 0) : make_float4(0.f,0.f,0.f,0.f);
    float4 pb1 = bv ? *(const float4*)(Bptr + 4) : make_float4(0.f,0.f,0.f,0.f);

    for (int k0 = 0; k0 < K; k0 += 16) {
        // stage (convert to tf32 bits)
        As[lk+0][lr] = f2tf32(pa0.x); As[lk+1][lr] = f2tf32(pa0.y);
        As[lk+2][lr] = f2tf32(pa0.z); As[lk+3][lr] = f2tf32(pa0.w);
        As[lk+4][lr] = f2tf32(pa1.x); As[lk+5][lr] = f2tf32(pa1.y);
        As[lk+6][lr] = f2tf32(pa1.z); As[lk+7][lr] = f2tf32(pa1.w);
        Bs[lk+0][lr] = f2tf32(pb0.x); Bs[lk+1][lr] = f2tf32(pb0.y);
        Bs[lk+2][lr] = f2tf32(pb0.z); Bs[lk+3][lr] = f2tf32(pb0.w);
        Bs[lk+4][lr] = f2tf32(pb1.x); Bs[lk+5][lr] = f2tf32(pb1.y);
        Bs[lk+6][lr] = f2tf32(pb1.z); Bs[lk+7][lr] = f2tf32(pb1.w);
        __syncthreads();

        // prefetch next tile (overlaps the MMAs below)
        if (k0 + 16 < K) {
            pa0 = *(const float4*)(Aptr + k0 + 16);
            pa1 = *(const float4*)(Aptr + k0 + 20);
            if (bv) {
                pb0 = *(const float4*)(Bptr + k0 + 16);
                pb1 = *(const float4*)(Bptr + k0 + 20);
            }
        }

        #pragma unroll
        for (int kk = 0; kk < 16; kk += 8) {
            uint32_t af[4][4], bf[4][2];
            #pragma unroll
            for (int mi = 0; mi < 4; mi++) {
                int ar = wm + mi*16 + group;
                af[mi][0] = As[kk+tg  ][ar];
                af[mi][1] = As[kk+tg  ][ar+8];
                af[mi][2] = As[kk+tg+4][ar];
                af[mi][3] = As[kk+tg+4][ar+8];
            }
            #pragma unroll
            for (int ni = 0; ni < 4; ni++) {
                int bc = wn + ni*8 + group;
                bf[ni][0] = Bs[kk+tg  ][bc];
                bf[ni][1] = Bs[kk+tg+4][bc];
            }
            #pragma unroll
            for (int mi = 0; mi < 4; mi++)
                #pragma unroll
                for (int ni = 0; ni < 4; ni++)
                    mma_tf32(acc[mi][ni], af[mi], bf[ni]);
        }
        __syncthreads();
    }

    // epilogue: c0:(g, 2tg) c1:(g, 2tg+1) c2:(g+8, 2tg) c3:(g+8, 2tg+1)
    #pragma unroll
    for (int mi = 0; mi < 4; mi++) {
        int gr0 = m0 + wm + mi*16 + group;
        #pragma unroll
        for (int ni = 0; ni < 4; ni++) {
            int gc = n0 + wn + ni*8 + tg*2;
            #pragma unroll
            for (int half = 0; half < 2; half++) {
                int gm = gr0 + half*8;
                #pragma unroll
                for (int j = 0; j < 2; j++) {
                    int gn = gc + j;
                    if (gn < Npad) {
                        float v = 0.f;
                        if (gn < N) {
                            v = acc[mi][ni][half*2 + j] + (bias ? bias[gn] : 0.f);
                            if (relu) v = fmaxf(v, 0.f);
                        }
                        C[(size_t)gm*ldc + gn] = v;
                    }
                }
            }
        }
    }
}

// ---------------- attention (one block per (b,h), 128 threads = 128 queries) ----------------
__global__ __launch_bounds__(128)
void attn_kernel(const float* __restrict__ qkv, float* __restrict__ probs,
                 float* __restrict__ attnout) {
    __shared__ float Ks[128][64];
    int bh = blockIdx.x;
    int b = bh / HH, h = bh % HH;
    int t = threadIdx.x;
    const float* base = qkv + (size_t)b*MM*(3*DD);
    for (int idx = t; idx < 128*64; idx += 128) {
        int j = idx >> 6, d = idx & 63;
        Ks[j][d] = base[(size_t)j*(3*DD) + DD + h*HD + d];
    }
    __syncthreads();
    float q[64];
    const float* qrow = base + (size_t)t*(3*DD) + h*HD;
    #pragma unroll
    for (int d0 = 0; d0 < 64; d0 += 4) {
        float4 v = *(const float4*)(qrow + d0);
        q[d0] = v.x; q[d0+1] = v.y; q[d0+2] = v.z; q[d0+3] = v.w;
    }
    float mx = -INFINITY;
    float* prow = probs + (size_t)bh*MM*MM;
    const float scale = 0.125f;
    for (int j = 0; j < 128; j++) {
        float s = 0.f;
        #pragma unroll
        for (int d = 0; d < 64; d++) s += q[d]*Ks[j][d];
        s *= scale;
        mx = fmaxf(mx, s);
        prow[(size_t)j*128 + t] = s;
    }
    __syncthreads();
    for (int idx = t; idx < 128*64; idx += 128) {
        int j = idx >> 6, d = idx & 63;
        Ks[j][d] = base[(size_t)j*(3*DD) + 2*DD + h*HD + d];
    }
    __syncthreads();
    float acc[64];
    #pragma unroll
    for (int d = 0; d < 64; d++) acc[d] = 0.f;
    float sum = 0.f;
    for (int j = 0; j < 128; j++) {
        float p = expf(prow[(size_t)j*128 + t] - mx);
        sum += p;
        #pragma unroll
        for (int d = 0; d < 64; d++) acc[d] += p*Ks[j][d];
    }
    float inv = 1.f/sum;
    float* orow = attnout + (size_t)(b*MM + t)*DD + h*HD;
    #pragma unroll
    for (int d = 0; d < 64; d++) orow[d] = acc[d]*inv;
}

// ---------------- fused residual + layernorm (in-place into x) ----------------
__global__ void add_ln_kernel(float* __restrict__ x, const float* __restrict__ y,
                              const float* __restrict__ w, const float* __restrict__ b) {
    __shared__ float buf[DD];
    int row = blockIdx.x, t = threadIdx.x;
    float* xr = x + (size_t)row*DD;
    const float* yr = y + (size_t)row*DD;
    float ls = 0.f;
    for (int d = t; d < DD; d += blockDim.x) {
        float v = xr[d] + yr[d];
        buf[d] = v;
        ls += v;
    }
    float mean = block_reduce_sum(ls) * (1.f/DD);
    float lv = 0.f;
    for (int d = t; d < DD; d += blockDim.x) {
        float c = buf[d] - mean;
        lv += c*c;
    }
    float var = block_reduce_sum(lv) * (1.f/DD);
    float r = rsqrtf(var + 1e-5f);
    for (int d = t; d < DD; d += blockDim.x)
        xr[d] = (buf[d] - mean)*r*w[d] + b[d];
}

// ---------------- pad cls_w2 [NE,100] -> [NE,128] ----------------
__global__ void pad_w2_kernel(const float* __restrict__ w2, float* __restrict__ w2p) {
    size_t i = (size_t)blockIdx.x*blockDim.x + threadIdx.x;
    if (i < (size_t)NE*KPAD) {
        int r = (int)(i >> 7), c = (int)(i & 127);
        w2p[i] = (c < 100) ? w2[(size_t)r*100 + c] : 0.f;
    }
}

// ---------------- launch ----------------
extern "C" void kernel_launch(void* const* d_in, const int* in_sizes, int n_in,
                              void* d_out, int out_size) {
    (void)in_sizes; (void)n_in; (void)out_size;
    const float* lhs    = (const float*)d_in[0];
    const int*   pos    = (const int*)d_in[1];     // int32
    const int*   mask   = (const int*)d_in[2];     // int32
    const float* attn_w = (const float*)d_in[3];
    const float* attn_b = (const float*)d_in[4];
    const float* qkv_w  = (const float*)d_in[5];
    const float* qkv_b  = (const float*)d_in[6];
    const float* out_w  = (const float*)d_in[7];
    const float* out_b  = (const float*)d_in[8];
    const float* ln1_w  = (const float*)d_in[9];
    const float* ln1_b  = (const float*)d_in[10];
    const float* ff1_w  = (const float*)d_in[11];
    const float* ff1_b  = (const float*)d_in[12];
    const float* ff2_w  = (const float*)d_in[13];
    const float* ff2_b  = (const float*)d_in[14];
    const float* ln2_w  = (const float*)d_in[15];
    const float* ln2_b  = (const float*)d_in[16];
    const float* cls_w1 = (const float*)d_in[17];
    const float* cls_w2 = (const float*)d_in[18];
    const float* cls_b2 = (const float*)d_in[19];
    float* out = (float*)d_out;

    float *x, *qkv, *attnout, *branch, *ffh, *probs, *tpad, *w2pad, *dl;
    cudaGetSymbolAddress((void**)&x,       g_x);
    cudaGetSymbolAddress((void**)&qkv,     g_qkv);
    cudaGetSymbolAddress((void**)&attnout, g_attnout);
    cudaGetSymbolAddress((void**)&branch,  g_branch);
    cudaGetSymbolAddress((void**)&ffh,     g_ffh);
    cudaGetSymbolAddress((void**)&probs,   g_probs);
    cudaGetSymbolAddress((void**)&tpad,    g_tpad);
    cudaGetSymbolAddress((void**)&w2pad,   g_w2pad);
    cudaGetSymbolAddress((void**)&dl,      g_dl);

    pad_w2_kernel<<<(NE*KPAD + 255)/256, 256>>>(cls_w2, w2pad);

    dot_kernel<<<BB*LL, 128>>>(lhs, attn_w, dl);
    pool_kernel<<<NROWS, 256>>>(lhs, pos, mask, dl, attn_b, x);

    for (int i = 0; i < NL; i++) {
        tgemm_nt<<<dim3(18,16), 256>>>(x, qkv_w + (size_t)i*3*DD*DD, qkv_b + (size_t)i*3*DD,
                                       qkv, NROWS, 3*DD, DD, DD, DD, 3*DD, 3*DD, 0);
        attn_kernel<<<BB*HH, 128>>>(qkv, probs, attnout);
        tgemm_nt<<<dim3(6,16), 256>>>(attnout, out_w + (size_t)i*DD*DD, out_b + (size_t)i*DD,
                                      branch, NROWS, DD, DD, DD, DD, DD, DD, 0);
        add_ln_kernel<<<NROWS, 256>>>(x, branch, ln1_w + (size_t)i*DD, ln1_b + (size_t)i*DD);
        tgemm_nt<<<dim3(24,16), 256>>>(x, ff1_w + (size_t)i*DFF*DD, ff1_b + (size_t)i*DFF,
                                       ffh, NROWS, DFF, DD, DD, DD, DFF, DFF, 1);
        tgemm_nt<<<dim3(6,16), 256>>>(ffh, ff2_w + (size_t)i*DD*DFF, ff2_b + (size_t)i*DD,
                                      branch, NROWS, DD, DFF, DFF, DFF, DD, DD, 0);
        add_ln_kernel<<<NROWS, 256>>>(x, branch, ln2_w + (size_t)i*DD, ln2_b + (size_t)i*DD);
    }

    tgemm_nt<<<dim3(1,16), 256>>>(x, cls_w1, (const float*)nullptr, tpad,
                                  NROWS, 100, DD, DD, DD, KPAD, KPAD, 0);
    tgemm_nt<<<dim3((NE + 127)/128, 16), 256>>>(tpad, w2pad, cls_b2, out,
                                                NROWS, NE, KPAD, KPAD, KPAD, NE, NE, 0);
}

// round 7
// speedup vs baseline: 2.0422x; 1.0376x over previous
#include <cuda_runtime.h>
#include <math.h>
#include <stdint.h>

// Problem constants
#define BB 16
#define MM 128
#define LL 32
#define SS 512
#define DD 768
#define HH 12
#define HD 64
#define DFF 3072
#define NL 4
#define NE 50000
#define NROWS (BB*MM)          // 2048
#define KPAD 128               // padded K for classifier stage 2

// ---------------- scratch (static device globals; no allocation) ----------------
__device__ __align__(16) float g_x[NROWS*DD];
__device__ __align__(16) float g_qkv[NROWS*3*DD];
__device__ __align__(16) float g_attnout[NROWS*DD];
__device__ __align__(16) float g_branch[NROWS*DD];
__device__ __align__(16) float g_ffh[NROWS*DFF];
__device__ __align__(16) float g_probs[BB*HH*MM*MM];
__device__ __align__(16) float g_tpad[NROWS*KPAD];
__device__ __align__(16) float g_w2pad[NE*KPAD];
__device__ __align__(16) float g_dl[BB*LL];

// ---------------- block reduction helper ----------------
__device__ __forceinline__ float block_reduce_sum(float v) {
    __shared__ float red[8];
    int lane = threadIdx.x & 31, wid = threadIdx.x >> 5, nw = (int)(blockDim.x >> 5);
    #pragma unroll
    for (int o = 16; o > 0; o >>= 1) v += __shfl_down_sync(0xffffffffu, v, o);
    __syncthreads();
    if (lane == 0) red[wid] = v;
    __syncthreads();
    float s = 0.f;
    for (int i = 0; i < nw; i++) s += red[i];
    return s;
}

// ---------------- mention pooling ----------------
__global__ void dot_kernel(const float* __restrict__ lhs, const float* __restrict__ aw,
                           float* __restrict__ dl) {
    int bl = blockIdx.x;                 // b*32 + l
    int b = bl >> 5, l = bl & 31;
    const float* r = lhs + ((size_t)b*SS + l)*DD;
    float s = 0.f;
    for (int d = threadIdx.x; d < DD; d += blockDim.x) s += r[d]*aw[d];
    s = block_reduce_sum(s);
    if (threadIdx.x == 0) dl[bl] = s;
}

// pos/mask are int32 (jax x64 disabled silently downcasts the int64 cast).
__global__ void pool_kernel(const float* __restrict__ lhs,
                            const int* __restrict__ pos,
                            const int* __restrict__ mask,
                            const float* __restrict__ dl,
                            const float* __restrict__ attn_b,
                            float* __restrict__ x) {
    int bm = blockIdx.x;                 // b*128 + m
    int b = bm >> 7;
    __shared__ float p[LL];
    __shared__ int s_vlen;
    if (threadIdx.x == 0) {
        int vlen = 0;
        if (mask[bm] != 0) {
            const int* pr = pos + (size_t)bm*LL;
            while (vlen < LL && pr[vlen] != -1) vlen++;
        }
        s_vlen = vlen;
        float ab = attn_b[0];
        float lg[LL];
        float mx = -INFINITY;
        for (int l = 0; l < LL; l++) {
            lg[l] = (l < vlen ? dl[b*LL + l] : 0.f) + ab;
            mx = fmaxf(mx, lg[l]);
        }
        float sum = 0.f;
        for (int l = 0; l < LL; l++) { float e = expf(lg[l]-mx); p[l] = e; sum += e; }
        float inv = 1.f/sum;
        for (int l = 0; l < LL; l++) p[l] *= inv;
    }
    __syncthreads();
    int vlen = s_vlen;
    float* xr = x + (size_t)bm*DD;
    for (int d = threadIdx.x; d < DD; d += blockDim.x) {
        float acc = 0.f;
        for (int l = 0; l < vlen; l++)
            acc += p[l] * lhs[((size_t)b*SS + l)*DD + d];
        xr[d] = acc;
    }
}

// ---------------- tf32 tensor-core GEMM, double-buffered ----------------
// C[M,N] = A[M,K] * B[N,K]^T (+bias)(+relu), fp32 accumulate via
// mma.sync.aligned.m16n8k8.row.col.f32.tf32.tf32.f32.
// 128x128 block tile, BK=16, 2-stage smem pipeline, 256 threads = 8 warps
// (2m x 4n), warp tile 64x32. M mult of 128, K mult of 16, lda/ldb mult of 4.
// Stores zeros for N <= n < Npad.

__device__ __forceinline__ uint32_t f2tf32(float x) {
    uint32_t y;
    asm("cvt.rna.tf32.f32 %0, %1;" : "=r"(y) : "f"(x));
    return y;
}

__device__ __forceinline__ void mma_tf32(float* c, const uint32_t* a, const uint32_t* b) {
    asm volatile(
        "mma.sync.aligned.m16n8k8.row.col.f32.tf32.tf32.f32 "
        "{%0,%1,%2,%3}, {%4,%5,%6,%7}, {%8,%9}, {%0,%1,%2,%3};\n"
        : "+f"(c[0]), "+f"(c[1]), "+f"(c[2]), "+f"(c[3])
        : "r"(a[0]), "r"(a[1]), "r"(a[2]), "r"(a[3]), "r"(b[0]), "r"(b[1]));
}

#define SMS 136   // smem row stride in words; 136 % 32 == 8 -> conflict-free

__global__ __launch_bounds__(256, 2)
void tgemm_nt(const float* __restrict__ A, const float* __restrict__ B,
              const float* __restrict__ bias, float* __restrict__ C,
              int M, int N, int K, int lda, int ldb, int ldc, int Npad, int relu) {
    __shared__ uint32_t As[2][16][SMS];   // [buf][k][m]
    __shared__ uint32_t Bs[2][16][SMS];   // [buf][k][n]
    int t = threadIdx.x;
    int m0 = blockIdx.y * 128;
    int n0 = blockIdx.x * 128;

    // staging: each thread owns one 32B chunk: row lr, k cols lk..lk+7
    int lr = t & 127;
    int lk = (t >> 7) * 8;
    const float* Aptr = A + (size_t)(m0 + lr)*lda + lk;
    bool bv = (n0 + lr) < N;
    const float* Bptr = B + (size_t)(n0 + lr)*ldb + lk;

    int warp  = t >> 5, lane = t & 31;
    int group = lane >> 2, tg = lane & 3;
    int wm = (warp >> 2) * 64;   // 0 / 64
    int wn = (warp & 3) * 32;    // 0..96

    float acc[4][4][4];
    #pragma unroll
    for (int mi = 0; mi < 4; mi++)
        #pragma unroll
        for (int ni = 0; ni < 4; ni++)
            #pragma unroll
            for (int r = 0; r < 4; r++) acc[mi][ni][r] = 0.f;

    // load + stage tile 0 into buffer 0
    float4 pa0 = *(const float4*)(Aptr + 0);
    float4 pa1 = *(const float4*)(Aptr + 4);
    float4 pb0 = bv ? *(const float4*)(Bptr + 0) : make_float4(0.f,0.f,0.f,0.f);
    float4 pb1 = bv ? *(const float4*)(Bptr + 4) : make_float4(0.f,0.f,0.f,0.f);
    As[0][lk+0][lr] = f2tf32(pa0.x); As[0][lk+1][lr] = f2tf32(pa0.y);
    As[0][lk+2][lr] = f2tf32(pa0.z); As[0][lk+3][lr] = f2tf32(pa0.w);
    As[0][lk+4][lr] = f2tf32(pa1.x); As[0][lk+5][lr] = f2tf32(pa1.y);
    As[0][lk+6][lr] = f2tf32(pa1.z); As[0][lk+7][lr] = f2tf32(pa1.w);
    Bs[0][lk+0][lr] = f2tf32(pb0.x); Bs[0][lk+1][lr] = f2tf32(pb0.y);
    Bs[0][lk+2][lr] = f2tf32(pb0.z); Bs[0][lk+3][lr] = f2tf32(pb0.w);
    Bs[0][lk+4][lr] = f2tf32(pb1.x); Bs[0][lk+5][lr] = f2tf32(pb1.y);
    Bs[0][lk+6][lr] = f2tf32(pb1.z); Bs[0][lk+7][lr] = f2tf32(pb1.w);
    __syncthreads();

    int cur = 0;
    for (int k0 = 16; k0 <= K; k0 += 16) {
        bool more = (k0 < K);
        // issue next tile's global loads first (overlap with MMA phase)
        if (more) {
            pa0 = *(const float4*)(Aptr + k0);
            pa1 = *(const float4*)(Aptr + k0 + 4);
            if (bv) {
                pb0 = *(const float4*)(Bptr + k0);
                pb1 = *(const float4*)(Bptr + k0 + 4);
            }
        }

        // compute on current buffer
        #pragma unroll
        for (int kk = 0; kk < 16; kk += 8) {
            uint32_t af[4][4], bf[4][2];
            #pragma unroll
            for (int mi = 0; mi < 4; mi++) {
                int ar = wm + mi*16 + group;
                af[mi][0] = As[cur][kk+tg  ][ar];
                af[mi][1] = As[cur][kk+tg  ][ar+8];
                af[mi][2] = As[cur][kk+tg+4][ar];
                af[mi][3] = As[cur][kk+tg+4][ar+8];
            }
            #pragma unroll
            for (int ni = 0; ni < 4; ni++) {
                int bc = wn + ni*8 + group;
                bf[ni][0] = Bs[cur][kk+tg  ][bc];
                bf[ni][1] = Bs[cur][kk+tg+4][bc];
            }
            #pragma unroll
            for (int mi = 0; mi < 4; mi++)
                #pragma unroll
                for (int ni = 0; ni < 4; ni++)
                    mma_tf32(acc[mi][ni], af[mi], bf[ni]);
        }

        // stage next tile into the other buffer
        if (more) {
            int nxt = cur ^ 1;
            As[nxt][lk+0][lr] = f2tf32(pa0.x); As[nxt][lk+1][lr] = f2tf32(pa0.y);
            As[nxt][lk+2][lr] = f2tf32(pa0.z); As[nxt][lk+3][lr] = f2tf32(pa0.w);
            As[nxt][lk+4][lr] = f2tf32(pa1.x); As[nxt][lk+5][lr] = f2tf32(pa1.y);
            As[nxt][lk+6][lr] = f2tf32(pa1.z); As[nxt][lk+7][lr] = f2tf32(pa1.w);
            Bs[nxt][lk+0][lr] = f2tf32(pb0.x); Bs[nxt][lk+1][lr] = f2tf32(pb0.y);
            Bs[nxt][lk+2][lr] = f2tf32(pb0.z); Bs[nxt][lk+3][lr] = f2tf32(pb0.w);
            Bs[nxt][lk+4][lr] = f2tf32(pb1.x); Bs[nxt][lk+5][lr] = f2tf32(pb1.y);
            Bs[nxt][lk+6][lr] = f2tf32(pb1.z); Bs[nxt][lk+7][lr] = f2tf32(pb1.w);
            __syncthreads();
            cur = nxt;
        }
    }

    // epilogue: c0:(g, 2tg) c1:(g, 2tg+1) c2:(g+8, 2tg) c3:(g+8, 2tg+1)
    #pragma unroll
    for (int mi = 0; mi < 4; mi++) {
        int gr0 = m0 + wm + mi*16 + group;
        #pragma unroll
        for (int ni = 0; ni < 4; ni++) {
            int gc = n0 + wn + ni*8 + tg*2;
            #pragma unroll
            for (int half = 0; half < 2; half++) {
                int gm = gr0 + half*8;
                if (gc + 1 < N) {
                    float v0 = acc[mi][ni][half*2+0] + (bias ? bias[gc]   : 0.f);
                    float v1 = acc[mi][ni][half*2+1] + (bias ? bias[gc+1] : 0.f);
                    if (relu) { v0 = fmaxf(v0, 0.f); v1 = fmaxf(v1, 0.f); }
                    *(float2*)&C[(size_t)gm*ldc + gc] = make_float2(v0, v1);
                } else {
                    #pragma unroll
                    for (int j = 0; j < 2; j++) {
                        int gn = gc + j;
                        if (gn < Npad) {
                            float v = 0.f;
                            if (gn < N) {
                                v = acc[mi][ni][half*2 + j] + (bias ? bias[gn] : 0.f);
                                if (relu) v = fmaxf(v, 0.f);
                            }
                            C[(size_t)gm*ldc + gn] = v;
                        }
                    }
                }
            }
        }
    }
}

// ---------------- attention (one block per (b,h), 128 threads = 128 queries) ----------------
__global__ __launch_bounds__(128)
void attn_kernel(const float* __restrict__ qkv, float* __restrict__ probs,
                 float* __restrict__ attnout) {
    __shared__ float Ks[128][64];
    int bh = blockIdx.x;
    int b = bh / HH, h = bh % HH;
    int t = threadIdx.x;
    const float* base = qkv + (size_t)b*MM*(3*DD);
    for (int idx = t; idx < 128*64; idx += 128) {
        int j = idx >> 6, d = idx & 63;
        Ks[j][d] = base[(size_t)j*(3*DD) + DD + h*HD + d];
    }
    __syncthreads();
    float q[64];
    const float* qrow = base + (size_t)t*(3*DD) + h*HD;
    #pragma unroll
    for (int d0 = 0; d0 < 64; d0 += 4) {
        float4 v = *(const float4*)(qrow + d0);
        q[d0] = v.x; q[d0+1] = v.y; q[d0+2] = v.z; q[d0+3] = v.w;
    }
    float mx = -INFINITY;
    float* prow = probs + (size_t)bh*MM*MM;
    const float scale = 0.125f;
    for (int j = 0; j < 128; j++) {
        float s = 0.f;
        #pragma unroll
        for (int d = 0; d < 64; d++) s += q[d]*Ks[j][d];
        s *= scale;
        mx = fmaxf(mx, s);
        prow[(size_t)j*128 + t] = s;
    }
    __syncthreads();
    for (int idx = t; idx < 128*64; idx += 128) {
        int j = idx >> 6, d = idx & 63;
        Ks[j][d] = base[(size_t)j*(3*DD) + 2*DD + h*HD + d];
    }
    __syncthreads();
    float acc[64];
    #pragma unroll
    for (int d = 0; d < 64; d++) acc[d] = 0.f;
    float sum = 0.f;
    for (int j = 0; j < 128; j++) {
        float p = expf(prow[(size_t)j*128 + t] - mx);
        sum += p;
        #pragma unroll
        for (int d = 0; d < 64; d++) acc[d] += p*Ks[j][d];
    }
    float inv = 1.f/sum;
    float* orow = attnout + (size_t)(b*MM + t)*DD + h*HD;
    #pragma unroll
    for (int d = 0; d < 64; d++) orow[d] = acc[d]*inv;
}

// ---------------- fused residual + layernorm (in-place into x) ----------------
__global__ void add_ln_kernel(float* __restrict__ x, const float* __restrict__ y,
                              const float* __restrict__ w, const float* __restrict__ b) {
    __shared__ float buf[DD];
    int row = blockIdx.x, t = threadIdx.x;
    float* xr = x + (size_t)row*DD;
    const float* yr = y + (size_t)row*DD;
    float ls = 0.f;
    for (int d = t; d < DD; d += blockDim.x) {
        float v = xr[d] + yr[d];
        buf[d] = v;
        ls += v;
    }
    float mean = block_reduce_sum(ls) * (1.f/DD);
    float lv = 0.f;
    for (int d = t; d < DD; d += blockDim.x) {
        float c = buf[d] - mean;
        lv += c*c;
    }
    float var = block_reduce_sum(lv) * (1.f/DD);
    float r = rsqrtf(var + 1e-5f);
    for (int d = t; d < DD; d += blockDim.x)
        xr[d] = (buf[d] - mean)*r*w[d] + b[d];
}

// ---------------- pad cls_w2 [NE,100] -> [NE,128] ----------------
__global__ void pad_w2_kernel(const float* __restrict__ w2, float* __restrict__ w2p) {
    size_t i = (size_t)blockIdx.x*blockDim.x + threadIdx.x;
    if (i < (size_t)NE*KPAD) {
        int r = (int)(i >> 7), c = (int)(i & 127);
        w2p[i] = (c < 100) ? w2[(size_t)r*100 + c] : 0.f;
    }
}

// ---------------- launch ----------------
extern "C" void kernel_launch(void* const* d_in, const int* in_sizes, int n_in,
                              void* d_out, int out_size) {
    (void)in_sizes; (void)n_in; (void)out_size;
    const float* lhs    = (const float*)d_in[0];
    const int*   pos    = (const int*)d_in[1];     // int32
    const int*   mask   = (const int*)d_in[2];     // int32
    const float* attn_w = (const float*)d_in[3];
    const float* attn_b = (const float*)d_in[4];
    const float* qkv_w  = (const float*)d_in[5];
    const float* qkv_b  = (const float*)d_in[6];
    const float* out_w  = (const float*)d_in[7];
    const float* out_b  = (const float*)d_in[8];
    const float* ln1_w  = (const float*)d_in[9];
    const float* ln1_b  = (const float*)d_in[10];
    const float* ff1_w  = (const float*)d_in[11];
    const float* ff1_b  = (const float*)d_in[12];
    const float* ff2_w  = (const float*)d_in[13];
    const float* ff2_b  = (const float*)d_in[14];
    const float* ln2_w  = (const float*)d_in[15];
    const float* ln2_b  = (const float*)d_in[16];
    const float* cls_w1 = (const float*)d_in[17];
    const float* cls_w2 = (const float*)d_in[18];
    const float* cls_b2 = (const float*)d_in[19];
    float* out = (float*)d_out;

    float *x, *qkv, *attnout, *branch, *ffh, *probs, *tpad, *w2pad, *dl;
    cudaGetSymbolAddress((void**)&x,       g_x);
    cudaGetSymbolAddress((void**)&qkv,     g_qkv);
    cudaGetSymbolAddress((void**)&attnout, g_attnout);
    cudaGetSymbolAddress((void**)&branch,  g_branch);
    cudaGetSymbolAddress((void**)&ffh,     g_ffh);
    cudaGetSymbolAddress((void**)&probs,   g_probs);
    cudaGetSymbolAddress((void**)&tpad,    g_tpad);
    cudaGetSymbolAddress((void**)&w2pad,   g_w2pad);
    cudaGetSymbolAddress((void**)&dl,      g_dl);

    pad_w2_kernel<<<(NE*KPAD + 255)/256, 256>>>(cls_w2, w2pad);

    dot_kernel<<<BB*LL, 128>>>(lhs, attn_w, dl);
    pool_kernel<<<NROWS, 256>>>(lhs, pos, mask, dl, attn_b, x);

    for (int i = 0; i < NL; i++) {
        tgemm_nt<<<dim3(18,16), 256>>>(x, qkv_w + (size_t)i*3*DD*DD, qkv_b + (size_t)i*3*DD,
                                       qkv, NROWS, 3*DD, DD, DD, DD, 3*DD, 3*DD, 0);
        attn_kernel<<<BB*HH, 128>>>(qkv, probs, attnout);
        tgemm_nt<<<dim3(6,16), 256>>>(attnout, out_w + (size_t)i*DD*DD, out_b + (size_t)i*DD,
                                      branch, NROWS, DD, DD, DD, DD, DD, DD, 0);
        add_ln_kernel<<<NROWS, 256>>>(x, branch, ln1_w + (size_t)i*DD, ln1_b + (size_t)i*DD);
        tgemm_nt<<<dim3(24,16), 256>>>(x, ff1_w + (size_t)i*DFF*DD, ff1_b + (size_t)i*DFF,
                                       ffh, NROWS, DFF, DD, DD, DD, DFF, DFF, 1);
        tgemm_nt<<<dim3(6,16), 256>>>(ffh, ff2_w + (size_t)i*DD*DFF, ff2_b + (size_t)i*DD,
                                      branch, NROWS, DD, DFF, DFF, DFF, DD, DD, 0);
        add_ln_kernel<<<NROWS, 256>>>(x, branch, ln2_w + (size_t)i*DD, ln2_b + (size_t)i*DD);
    }

    tgemm_nt<<<dim3(1,16), 256>>>(x, cls_w1, (const float*)nullptr, tpad,
                                  NROWS, 100, DD, DD, DD, KPAD, KPAD, 0);
    tgemm_nt<<<dim3((NE + 127)/128, 16), 256>>>(tpad, w2pad, cls_b2, out,
                                                NROWS, NE, KPAD, KPAD, KPAD, NE, NE, 0);
}